// round 1
// baseline (speedup 1.0000x reference)
#include <cuda_runtime.h>
#include <float.h>
#include <math.h>

#define BB 8
#define NN 2048
#define DD 512

// Scratch (allocation-free contract: __device__ globals only)
__device__ float g_xx[BB * NN];
__device__ float g_dist[(size_t)BB * NN * NN];   // 134 MB

// ---------------------------------------------------------------------------
// Kernel 1: row squared norms. 8 warps/block, 1 warp per row.
// ---------------------------------------------------------------------------
__global__ __launch_bounds__(256) void xx_kernel(const float* __restrict__ put) {
    int row  = blockIdx.x * 8 + (threadIdx.x >> 5);   // 0 .. B*N-1
    int lane = threadIdx.x & 31;
    const float* p = put + (size_t)row * DD;
    float s = 0.f;
#pragma unroll
    for (int f = 0; f < 4; f++) {
        float4 v = *(const float4*)(p + f * 128 + lane * 4);
        s = fmaf(v.x, v.x, s);
        s = fmaf(v.y, v.y, s);
        s = fmaf(v.z, v.z, s);
        s = fmaf(v.w, v.w, s);
    }
#pragma unroll
    for (int off = 16; off; off >>= 1)
        s += __shfl_xor_sync(0xffffffffu, s, off);
    if (lane == 0) g_xx[row] = s;
}

// ---------------------------------------------------------------------------
// Kernel 2: distance tiles via fp32 SGEMM, 128x128 tile, BK=8, 8x8 per thread.
// Symmetry: only tiles with by <= bx are computed; off-diagonal mirrored.
// ---------------------------------------------------------------------------
#define BM 128
#define BN 128
#define BK 8
#define PITCH 132   // conflict-free STS, 16B-aligned rows for LDS.128

__global__ __launch_bounds__(256) void dist_kernel(const float* __restrict__ put) {
    int bx = blockIdx.x, by = blockIdx.y, b = blockIdx.z;
    if (by > bx) return;   // triangular

    __shared__ float As[BK][PITCH];
    __shared__ float Bs[BK][PITCH];

    int t  = threadIdx.x;
    int tx = t & 15;      // 0..15 -> i micro
    int ty = t >> 4;      // 0..15 -> j micro

    const float* base = put + (size_t)b * NN * DD;
    int j0 = by * BM;
    int i0 = bx * BN;

    // load mapping: each thread loads one float4 of A and one of B per k-chunk
    int lr = t >> 1;          // 0..127 : row within tile
    int lk = (t & 1) * 4;     // 0 or 4 : k offset
    const float* aptr = base + (size_t)(j0 + lr) * DD + lk;
    const float* bptr = base + (size_t)(i0 + lr) * DD + lk;

    float acc[8][8];
#pragma unroll
    for (int u = 0; u < 8; u++)
#pragma unroll
        for (int v = 0; v < 8; v++) acc[u][v] = 0.f;

    for (int kt = 0; kt < DD; kt += BK) {
        float4 av = *(const float4*)(aptr + kt);
        float4 bv = *(const float4*)(bptr + kt);
        As[lk + 0][lr] = av.x; As[lk + 1][lr] = av.y;
        As[lk + 2][lr] = av.z; As[lk + 3][lr] = av.w;
        Bs[lk + 0][lr] = bv.x; Bs[lk + 1][lr] = bv.y;
        Bs[lk + 2][lr] = bv.z; Bs[lk + 3][lr] = bv.w;
        __syncthreads();

#pragma unroll
        for (int kk = 0; kk < BK; kk++) {
            float4 a0 = *(const float4*)&As[kk][ty * 8];
            float4 a1 = *(const float4*)&As[kk][ty * 8 + 4];
            float4 b0 = *(const float4*)&Bs[kk][tx * 8];
            float4 b1 = *(const float4*)&Bs[kk][tx * 8 + 4];
            float a[8] = {a0.x, a0.y, a0.z, a0.w, a1.x, a1.y, a1.z, a1.w};
            float c[8] = {b0.x, b0.y, b0.z, b0.w, b1.x, b1.y, b1.z, b1.w};
#pragma unroll
            for (int u = 0; u < 8; u++)
#pragma unroll
                for (int v = 0; v < 8; v++)
                    acc[u][v] = fmaf(a[u], c[v], acc[u][v]);
        }
        __syncthreads();
    }

    // epilogue: dist = sqrt(max(xx_j + xx_i - 2*gram, 0))
    int jj = j0 + ty * 8;
    int ii = i0 + tx * 8;
    float xj[8], xi[8];
#pragma unroll
    for (int u = 0; u < 8; u++) xj[u] = g_xx[b * NN + jj + u];
#pragma unroll
    for (int v = 0; v < 8; v++) xi[v] = g_xx[b * NN + ii + v];

#pragma unroll
    for (int u = 0; u < 8; u++)
#pragma unroll
        for (int v = 0; v < 8; v++) {
            float d2 = (xj[u] + xi[v]) - 2.0f * acc[u][v];
            acc[u][v] = sqrtf(fmaxf(d2, 0.0f));
        }

    // normal store: rows jj+u, cols ii..ii+7
#pragma unroll
    for (int u = 0; u < 8; u++) {
        float* dst = &g_dist[((size_t)b * NN + jj + u) * NN + ii];
        *(float4*)(dst)     = make_float4(acc[u][0], acc[u][1], acc[u][2], acc[u][3]);
        *(float4*)(dst + 4) = make_float4(acc[u][4], acc[u][5], acc[u][6], acc[u][7]);
    }
    // mirror store for off-diagonal tiles: rows ii+v, cols jj..jj+7
    if (bx != by) {
#pragma unroll
        for (int v = 0; v < 8; v++) {
            float* dst = &g_dist[((size_t)b * NN + ii + v) * NN + jj];
            *(float4*)(dst)     = make_float4(acc[0][v], acc[1][v], acc[2][v], acc[3][v]);
            *(float4*)(dst + 4) = make_float4(acc[4][v], acc[5][v], acc[6][v], acc[7][v]);
        }
    }
}

// ---------------------------------------------------------------------------
// Kernel 3: per-row top-16 smallest (stable: tie -> lower index), write row.
// One block of 256 threads per (b, j) row.
// ---------------------------------------------------------------------------
__device__ __forceinline__ void cmin(float& v, int& i, float v2, int i2) {
    if (v2 < v || (v2 == v && i2 < i)) { v = v2; i = i2; }
}

__global__ __launch_bounds__(256) void topk_kernel(float* __restrict__ out) {
    int row = blockIdx.x;       // 0 .. B*N-1
    int tid = threadIdx.x;
    int lane = tid & 31;
    int wrp  = tid >> 5;

    __shared__ float vals[NN];      // distance row, later reused as output row
    __shared__ float wv[8];
    __shared__ int   wi[8];
    __shared__ int   winner;
    __shared__ int   widx[16];

    const float* drow = g_dist + (size_t)row * NN;
#pragma unroll
    for (int q = 0; q < 2; q++) {
        float4 v = *(const float4*)(drow + tid * 8 + q * 4);
        *(float4*)&vals[tid * 8 + q * 4] = v;
    }
    __syncthreads();

    for (int it = 0; it < 16; it++) {
        float lv = FLT_MAX;
        int   li = NN;
#pragma unroll
        for (int q = 0; q < 8; q++) cmin(lv, li, vals[tid * 8 + q], tid * 8 + q);
        // warp reduce (val, idx)
#pragma unroll
        for (int off = 16; off; off >>= 1) {
            float ov = __shfl_down_sync(0xffffffffu, lv, off);
            int   oi = __shfl_down_sync(0xffffffffu, li, off);
            cmin(lv, li, ov, oi);
        }
        if (lane == 0) { wv[wrp] = lv; wi[wrp] = li; }
        __syncthreads();
        if (tid == 0) {
            float bv = wv[0]; int bi = wi[0];
#pragma unroll
            for (int w = 1; w < 8; w++) cmin(bv, bi, wv[w], wi[w]);
            widx[it] = bi;
            winner   = bi;
            vals[bi] = FLT_MAX;     // remove winner
        }
        __syncthreads();
        (void)winner;
    }

    // reuse vals as the output row: zero, set 16 ones, store
    __syncthreads();
#pragma unroll
    for (int q = 0; q < 2; q++)
        *(float4*)&vals[tid * 8 + q * 4] = make_float4(0.f, 0.f, 0.f, 0.f);
    __syncthreads();
    if (tid < 16) vals[widx[tid]] = 1.0f;
    __syncthreads();

    float* orow = out + (size_t)row * NN;
#pragma unroll
    for (int q = 0; q < 2; q++)
        *(float4*)(orow + tid * 8 + q * 4) = *(float4*)&vals[tid * 8 + q * 4];
}

// ---------------------------------------------------------------------------
extern "C" void kernel_launch(void* const* d_in, const int* in_sizes, int n_in,
                              void* d_out, int out_size) {
    const float* put = (const float*)d_in[0];
    float* out = (float*)d_out;

    xx_kernel<<<(BB * NN) / 8, 256>>>(put);
    dim3 grid(NN / BN, NN / BM, BB);
    dist_kernel<<<grid, 256>>>(put);
    topk_kernel<<<BB * NN, 256>>>(out);
}